// round 1
// baseline (speedup 1.0000x reference)
#include <cuda_runtime.h>
#include <math.h>

#define A_NUM 3
#define DIMS  2048
#define NPAD  16      // 12 bbox + 3 conf + 1 zero pad
#define CONF_THRESH 0.5f

// Fused, padded weight matrix: g_Wp[k][j], j in [0,16). j<12: W_bbox, 12<=j<15: W_conf, j=15: 0.
// 2048*16*4 = 128KB static device scratch (allowed; no allocations).
__device__ float g_Wp[DIMS * NPAD];

__global__ void prep_kernel(const float* __restrict__ Wb, const float* __restrict__ Wc) {
    int i = blockIdx.x * blockDim.x + threadIdx.x;
    if (i >= DIMS * NPAD) return;
    int k = i >> 4;
    int j = i & 15;
    float v = 0.0f;
    if (j < 12)      v = Wb[k * 12 + j];
    else if (j < 15) v = Wc[k * 3 + (j - 12)];
    g_Wp[i] = v;
}

// One warp processes 4 rows (R=4 row blocking). K=2048 partitioned across 32 lanes
// via float4 loads. Accumulators are f32x2 pairs over output index j (8 pairs = 16 outs).
__global__ __launch_bounds__(256, 2)
void det_kernel(const float4* __restrict__ feat4,   // [rows][512] float4
                const float*  __restrict__ b_bbox,  // [12]
                const float*  __restrict__ b_conf,  // [3]
                float* __restrict__ out_boxes,      // [rows][3][4]
                float* __restrict__ out_conf,       // [rows][3]
                float* __restrict__ out_valid,      // [rows][3] (1.0/0.0)
                int rows)
{
    int gwarp = (blockIdx.x * blockDim.x + threadIdx.x) >> 5;
    int lane  = threadIdx.x & 31;
    int r0 = gwarp * 4;
    if (r0 >= rows) return;

    // acc[r][p] holds (partial_out[2p], partial_out[2p+1]) as packed f32x2
    unsigned long long acc[4][8];
    #pragma unroll
    for (int r = 0; r < 4; r++)
        #pragma unroll
        for (int p = 0; p < 8; p++) acc[r][p] = 0ULL;

    const unsigned long long* __restrict__ Wp2 =
        reinterpret_cast<const unsigned long long*>(g_Wp);

    // K loop: 16 chunks of 128 k's; each lane owns k = c*128 + 4*lane + e
    for (int c = 0; c < 16; c++) {
        float4 f[4];
        #pragma unroll
        for (int r = 0; r < 4; r++)
            f[r] = feat4[(size_t)(r0 + r) * (DIMS / 4) + c * 32 + lane];

        int kbase = c * 128 + 4 * lane;
        #pragma unroll
        for (int e = 0; e < 4; e++) {
            // 8 aligned 64-bit W-pair loads, reused across the 4 rows
            unsigned long long w[8];
            const unsigned long long* wrow = Wp2 + (size_t)(kbase + e) * 8;
            #pragma unroll
            for (int p = 0; p < 8; p++) w[p] = wrow[p];

            #pragma unroll
            for (int r = 0; r < 4; r++) {
                float fe = (e == 0) ? f[r].x : (e == 1) ? f[r].y : (e == 2) ? f[r].z : f[r].w;
                unsigned long long f2;
                asm("mov.b64 %0, {%1, %1};" : "=l"(f2) : "r"(__float_as_uint(fe)));
                #pragma unroll
                for (int p = 0; p < 8; p++) {
                    asm("fma.rn.f32x2 %0, %1, %2, %0;"
                        : "+l"(acc[r][p]) : "l"(f2), "l"(w[p]));
                }
            }
        }
    }

    // Unpack to 15 scalar partials per row, butterfly-reduce across the warp (K dim)
    float s[4][15];
    #pragma unroll
    for (int r = 0; r < 4; r++) {
        #pragma unroll
        for (int p = 0; p < 8; p++) {
            float lo = __uint_as_float((unsigned int)(acc[r][p] & 0xFFFFFFFFULL));
            float hi = __uint_as_float((unsigned int)(acc[r][p] >> 32));
            s[r][2 * p] = lo;
            if (2 * p + 1 < 15) s[r][2 * p + 1] = hi;
        }
    }
    #pragma unroll
    for (int off = 16; off >= 1; off >>= 1) {
        #pragma unroll
        for (int r = 0; r < 4; r++)
            #pragma unroll
            for (int j = 0; j < 15; j++)
                s[r][j] += __shfl_xor_sync(0xFFFFFFFFu, s[r][j], off);
    }

    // Epilogue: lanes 0..3 finalize rows r0..r0+3
    if (lane < 4) {
        int row = r0 + lane;
        if (row < rows) {
            float bbox[12];
            #pragma unroll
            for (int j = 0; j < 12; j++) bbox[j] = s[lane][j] + b_bbox[j];

            float conf[3];
            int   idx[3] = {0, 1, 2};
            #pragma unroll
            for (int a = 0; a < 3; a++) {
                float logit = s[lane][12 + a] + b_conf[a];
                conf[a] = 1.0f / (1.0f + expf(-logit));
            }

            // Stable descending sort of 3 (matches lax.top_k: lower index wins ties)
            if (conf[0] < conf[1]) { float t = conf[0]; conf[0] = conf[1]; conf[1] = t;
                                     int ti = idx[0]; idx[0] = idx[1]; idx[1] = ti; }
            if (conf[1] < conf[2]) { float t = conf[1]; conf[1] = conf[2]; conf[2] = t;
                                     int ti = idx[1]; idx[1] = idx[2]; idx[2] = ti; }
            if (conf[0] < conf[1]) { float t = conf[0]; conf[0] = conf[1]; conf[1] = t;
                                     int ti = idx[0]; idx[0] = idx[1]; idx[1] = ti; }

            #pragma unroll
            for (int slot = 0; slot < 3; slot++) {
                bool v = conf[slot] > CONF_THRESH;
                out_conf [row * 3 + slot] = conf[slot];
                out_valid[row * 3 + slot] = v ? 1.0f : 0.0f;
                #pragma unroll
                for (int i = 0; i < 4; i++)
                    out_boxes[row * 12 + slot * 4 + i] =
                        v ? bbox[idx[slot] * 4 + i] : 0.0f;
            }
        }
    }
}

extern "C" void kernel_launch(void* const* d_in, const int* in_sizes, int n_in,
                              void* d_out, int out_size) {
    const float* features = (const float*)d_in[0];  // [B,T,D] f32
    const float* W_bbox   = (const float*)d_in[1];  // [D,12]
    const float* b_bbox   = (const float*)d_in[2];  // [12]
    const float* W_conf   = (const float*)d_in[3];  // [D,3]
    const float* b_conf   = (const float*)d_in[4];  // [3]

    int rows = in_sizes[0] / DIMS;  // B*T = 16384

    float* out       = (float*)d_out;
    float* out_boxes = out;                           // rows*12
    float* out_conf  = out + (size_t)rows * 12;       // rows*3
    float* out_valid = out + (size_t)rows * 15;       // rows*3

    prep_kernel<<<(DIMS * NPAD + 255) / 256, 256>>>(W_bbox, W_conf);

    int nwarps  = (rows + 3) / 4;          // one warp per 4 rows
    int threads = 256;
    int blocks  = (nwarps * 32 + threads - 1) / threads;
    det_kernel<<<blocks, threads>>>((const float4*)features, b_bbox, b_conf,
                                    out_boxes, out_conf, out_valid, rows);
}

// round 2
// speedup vs baseline: 3.1066x; 3.1066x over previous
#include <cuda_runtime.h>
#include <math.h>

#define DIMS   2048
#define NPAD   16          // 12 bbox + 3 conf + 1 zero pad (accumulated outputs)
#define WS_STRIDE 18       // smem floats per k-row (72B, 8B-aligned, conflict-free)
#define CONF_THRESH 0.5f
#define THREADS 512
#define NWARPS  (THREADS / 32)
#define SMEM_BYTES (DIMS * WS_STRIDE * 4)

typedef unsigned long long ull;

// One warp processes 4 rows. k partitioned stride-1 across lanes: k = c*32 + lane.
// W held in shared memory [2048][18] (cols 0..11 bbox, 12..14 conf, 15..17 zero).
__global__ __launch_bounds__(THREADS, 1)
void det_kernel(const float* __restrict__ feat,     // [rows][2048]
                const float* __restrict__ W_bbox,   // [2048][12]
                const float* __restrict__ W_conf,   // [2048][3]
                const float* __restrict__ b_bbox,   // [12]
                const float* __restrict__ b_conf,   // [3]
                float* __restrict__ out_boxes,      // [rows][3][4]
                float* __restrict__ out_conf,       // [rows][3]
                float* __restrict__ out_valid,      // [rows][3]
                int rows)
{
    extern __shared__ float ws[];   // [DIMS][WS_STRIDE]

    // ---- Stage W into padded smem (disjoint writes; one sync) ----
    for (int i = threadIdx.x; i < DIMS * 12; i += THREADS) {
        int k = i / 12, j = i % 12;
        ws[k * WS_STRIDE + j] = W_bbox[i];
    }
    for (int i = threadIdx.x; i < DIMS * 3; i += THREADS) {
        int k = i / 3, j = i % 3;
        ws[k * WS_STRIDE + 12 + j] = W_conf[i];
        ws[k * WS_STRIDE + 15 + j] = 0.0f;   // pad cols 15..17
    }
    __syncthreads();

    int lane = threadIdx.x & 31;
    int warp = threadIdx.x >> 5;
    int ntasks = rows >> 2;                  // 4 rows per task

    for (int t = blockIdx.x * NWARPS + warp; t < ntasks; t += gridDim.x * NWARPS) {
        int r0 = t * 4;
        const float* fbase = feat + (size_t)r0 * DIMS + lane;

        ull acc[4][8];
        #pragma unroll
        for (int r = 0; r < 4; r++)
            #pragma unroll
            for (int p = 0; p < 8; p++) acc[r][p] = 0ULL;

        // Software pipeline: prefetch depth 2 on feature chunks
        float fA[4], fB[4];
        #pragma unroll
        for (int r = 0; r < 4; r++) fA[r] = fbase[r * DIMS + 0 * 32];
        #pragma unroll
        for (int r = 0; r < 4; r++) fB[r] = fbase[r * DIMS + 1 * 32];

        for (int c = 0; c < 64; c++) {
            float fn[4];
            if (c + 2 < 64) {
                #pragma unroll
                for (int r = 0; r < 4; r++) fn[r] = fbase[r * DIMS + (c + 2) * 32];
            }

            // Conflict-free LDS.64 of this lane's W row (k = c*32 + lane)
            const ull* wrow = reinterpret_cast<const ull*>(ws + (c * 32 + lane) * WS_STRIDE);
            ull w[8];
            #pragma unroll
            for (int p = 0; p < 8; p++) w[p] = wrow[p];

            #pragma unroll
            for (int r = 0; r < 4; r++) {
                ull f2;
                asm("mov.b64 %0, {%1, %1};" : "=l"(f2) : "r"(__float_as_uint(fA[r])));
                #pragma unroll
                for (int p = 0; p < 8; p++) {
                    asm("fma.rn.f32x2 %0, %1, %2, %0;"
                        : "+l"(acc[r][p]) : "l"(f2), "l"(w[p]));
                }
            }

            #pragma unroll
            for (int r = 0; r < 4; r++) { fA[r] = fB[r]; fB[r] = fn[r]; }
        }

        // ---- Unpack and butterfly-reduce 15 partials per row over the warp ----
        float s[4][15];
        #pragma unroll
        for (int r = 0; r < 4; r++) {
            #pragma unroll
            for (int p = 0; p < 8; p++) {
                float lo = __uint_as_float((unsigned)(acc[r][p] & 0xFFFFFFFFULL));
                float hi = __uint_as_float((unsigned)(acc[r][p] >> 32));
                s[r][2 * p] = lo;
                if (2 * p + 1 < 15) s[r][2 * p + 1] = hi;
            }
        }
        #pragma unroll
        for (int off = 16; off >= 1; off >>= 1) {
            #pragma unroll
            for (int r = 0; r < 4; r++)
                #pragma unroll
                for (int j = 0; j < 15; j++)
                    s[r][j] += __shfl_xor_sync(0xFFFFFFFFu, s[r][j], off);
        }

        // ---- Epilogue: lanes 0..3 finalize rows r0..r0+3 ----
        if (lane < 4) {
            int row = r0 + lane;

            float bbox[12];
            #pragma unroll
            for (int j = 0; j < 12; j++) bbox[j] = s[lane][j] + b_bbox[j];

            float conf[3];
            int   idx[3] = {0, 1, 2};
            #pragma unroll
            for (int a = 0; a < 3; a++) {
                float logit = s[lane][12 + a] + b_conf[a];
                conf[a] = 1.0f / (1.0f + expf(-logit));
            }

            // Stable descending sort of 3 (lower index wins ties, matches lax.top_k)
            if (conf[0] < conf[1]) { float tv = conf[0]; conf[0] = conf[1]; conf[1] = tv;
                                     int ti = idx[0]; idx[0] = idx[1]; idx[1] = ti; }
            if (conf[1] < conf[2]) { float tv = conf[1]; conf[1] = conf[2]; conf[2] = tv;
                                     int ti = idx[1]; idx[1] = idx[2]; idx[2] = ti; }
            if (conf[0] < conf[1]) { float tv = conf[0]; conf[0] = conf[1]; conf[1] = tv;
                                     int ti = idx[0]; idx[0] = idx[1]; idx[1] = ti; }

            #pragma unroll
            for (int slot = 0; slot < 3; slot++) {
                bool v = conf[slot] > CONF_THRESH;
                out_conf [row * 3 + slot] = conf[slot];
                out_valid[row * 3 + slot] = v ? 1.0f : 0.0f;
                #pragma unroll
                for (int i = 0; i < 4; i++)
                    out_boxes[row * 12 + slot * 4 + i] =
                        v ? bbox[idx[slot] * 4 + i] : 0.0f;
            }
        }
    }
}

extern "C" void kernel_launch(void* const* d_in, const int* in_sizes, int n_in,
                              void* d_out, int out_size) {
    const float* features = (const float*)d_in[0];
    const float* W_bbox   = (const float*)d_in[1];
    const float* b_bbox   = (const float*)d_in[2];
    const float* W_conf   = (const float*)d_in[3];
    const float* b_conf   = (const float*)d_in[4];

    int rows = in_sizes[0] / DIMS;   // 16384

    float* out       = (float*)d_out;
    float* out_boxes = out;
    float* out_conf  = out + (size_t)rows * 12;
    float* out_valid = out + (size_t)rows * 15;

    cudaFuncSetAttribute(det_kernel,
                         cudaFuncAttributeMaxDynamicSharedMemorySize, SMEM_BYTES);

    // 128 CTAs x 16 warps x 2 tasks = 4096 tasks exactly (perfect balance)
    det_kernel<<<128, THREADS, SMEM_BYTES>>>(features, W_bbox, W_conf,
                                             b_bbox, b_conf,
                                             out_boxes, out_conf, out_valid, rows);
}

// round 3
// speedup vs baseline: 4.0390x; 1.3001x over previous
#include <cuda_runtime.h>
#include <math.h>

#define DIMS   2048
#define CONF_THRESH 0.5f
#define THREADS 448
#define NWARPS  (THREADS / 32)
#define GRID    148
#define PLANE_STRIDE 20                      // floats per k-row in a plane (80B, 16B-aligned)
#define PLANE_FLOATS (512 * PLANE_STRIDE)    // 10240 floats per e-plane
#define SMEM_BYTES   (4 * PLANE_FLOATS * 4)  // 163840 B

typedef unsigned long long ull;

// One warp : 4 rows. k = c*128 + 4*lane + e  (c in 0..15, e in 0..3).
// W in smem as 4 e-planes: plane e holds k-rows with (k&3)==e at index (k>>2), stride 20 floats.
// LDS.128 bank-conflict-free: lane bank base 20*l mod 32 covers all 32 banks per 8-lane phase.
__global__ __launch_bounds__(THREADS, 1)
void det_kernel(const float4* __restrict__ feat4,   // [rows][512]
                const float*  __restrict__ W_bbox,  // [2048][12]
                const float*  __restrict__ W_conf,  // [2048][3]
                const float*  __restrict__ b_bbox,  // [12]
                const float*  __restrict__ b_conf,  // [3]
                float* __restrict__ out_boxes,      // [rows][3][4]
                float* __restrict__ out_conf,       // [rows][3]
                float* __restrict__ out_valid,      // [rows][3]
                int rows)
{
    extern __shared__ float ws[];

    // ---- Stage W into e-planes: ws[(k&3)*PLANE_FLOATS + (k>>2)*20 + j], j in 0..15 ----
    for (int i = threadIdx.x; i < DIMS * 16; i += THREADS) {
        int k = i >> 4, j = i & 15;
        float v = 0.0f;
        if (j < 12)      v = W_bbox[k * 12 + j];
        else if (j < 15) v = W_conf[k * 3 + (j - 12)];
        ws[(k & 3) * PLANE_FLOATS + (k >> 2) * PLANE_STRIDE + j] = v;
    }
    __syncthreads();

    int lane = threadIdx.x & 31;
    int warp = threadIdx.x >> 5;
    int ntasks = rows >> 2;

    for (int t = blockIdx.x * NWARPS + warp; t < ntasks; t += GRID * NWARPS) {
        int r0 = t * 4;
        const float4* fbase = feat4 + (size_t)r0 * (DIMS / 4) + lane;

        ull acc[4][8];
        #pragma unroll
        for (int r = 0; r < 4; r++)
            #pragma unroll
            for (int p = 0; p < 8; p++) acc[r][p] = 0ULL;

        // Depth-1 prefetch on 16-byte feature chunks (streaming loads, bypass L1)
        float4 fA[4], fN[4];
        #pragma unroll
        for (int r = 0; r < 4; r++) fA[r] = __ldcs(fbase + (size_t)r * (DIMS / 4));

        #pragma unroll 1
        for (int c = 0; c < 16; c++) {
            int cn = (c + 1 < 16) ? c + 1 : 15;
            #pragma unroll
            for (int r = 0; r < 4; r++)
                fN[r] = __ldcs(fbase + (size_t)r * (DIMS / 4) + cn * 32);

            int rowidx = (c * 32 + lane) * PLANE_STRIDE;

            #pragma unroll
            for (int e = 0; e < 4; e++) {
                // 4x LDS.128 of this lane's 16 W floats (8 ull pairs), conflict-free
                const ulonglong2* wrow =
                    reinterpret_cast<const ulonglong2*>(ws + e * PLANE_FLOATS + rowidx);
                ulonglong2 w01 = wrow[0], w23 = wrow[1], w45 = wrow[2], w67 = wrow[3];
                ull w[8] = { w01.x, w01.y, w23.x, w23.y, w45.x, w45.y, w67.x, w67.y };

                #pragma unroll
                for (int r = 0; r < 4; r++) {
                    float fe = (e == 0) ? fA[r].x : (e == 1) ? fA[r].y
                             : (e == 2) ? fA[r].z : fA[r].w;
                    ull f2;
                    asm("mov.b64 %0, {%1, %1};" : "=l"(f2) : "r"(__float_as_uint(fe)));
                    #pragma unroll
                    for (int p = 0; p < 8; p++) {
                        asm("fma.rn.f32x2 %0, %1, %2, %0;"
                            : "+l"(acc[r][p]) : "l"(f2), "l"(w[p]));
                    }
                }
            }

            #pragma unroll
            for (int r = 0; r < 4; r++) fA[r] = fN[r];
        }

        // ---- Unpack + butterfly reduce 15 partials/row over the warp ----
        float s[4][15];
        #pragma unroll
        for (int r = 0; r < 4; r++) {
            #pragma unroll
            for (int p = 0; p < 8; p++) {
                float lo = __uint_as_float((unsigned)(acc[r][p] & 0xFFFFFFFFULL));
                float hi = __uint_as_float((unsigned)(acc[r][p] >> 32));
                s[r][2 * p] = lo;
                if (2 * p + 1 < 15) s[r][2 * p + 1] = hi;
            }
        }
        #pragma unroll
        for (int off = 16; off >= 1; off >>= 1) {
            #pragma unroll
            for (int r = 0; r < 4; r++)
                #pragma unroll
                for (int j = 0; j < 15; j++)
                    s[r][j] += __shfl_xor_sync(0xFFFFFFFFu, s[r][j], off);
        }

        // ---- Epilogue: lanes 0..3 finalize rows r0..r0+3 ----
        if (lane < 4) {
            int row = r0 + lane;

            float bbox[12];
            #pragma unroll
            for (int j = 0; j < 12; j++) bbox[j] = s[lane][j] + b_bbox[j];

            float conf[3];
            int   idx[3] = {0, 1, 2};
            #pragma unroll
            for (int a = 0; a < 3; a++) {
                float logit = s[lane][12 + a] + b_conf[a];
                conf[a] = 1.0f / (1.0f + expf(-logit));
            }

            // Stable descending sort of 3 (lower index wins ties, matches lax.top_k)
            if (conf[0] < conf[1]) { float tv = conf[0]; conf[0] = conf[1]; conf[1] = tv;
                                     int ti = idx[0]; idx[0] = idx[1]; idx[1] = ti; }
            if (conf[1] < conf[2]) { float tv = conf[1]; conf[1] = conf[2]; conf[2] = tv;
                                     int ti = idx[1]; idx[1] = idx[2]; idx[2] = ti; }
            if (conf[0] < conf[1]) { float tv = conf[0]; conf[0] = conf[1]; conf[1] = tv;
                                     int ti = idx[0]; idx[0] = idx[1]; idx[1] = ti; }

            #pragma unroll
            for (int slot = 0; slot < 3; slot++) {
                bool v = conf[slot] > CONF_THRESH;
                out_conf [row * 3 + slot] = conf[slot];
                out_valid[row * 3 + slot] = v ? 1.0f : 0.0f;
                #pragma unroll
                for (int i = 0; i < 4; i++)
                    out_boxes[row * 12 + slot * 4 + i] =
                        v ? bbox[idx[slot] * 4 + i] : 0.0f;
            }
        }
    }
}

extern "C" void kernel_launch(void* const* d_in, const int* in_sizes, int n_in,
                              void* d_out, int out_size) {
    const float* features = (const float*)d_in[0];
    const float* W_bbox   = (const float*)d_in[1];
    const float* b_bbox   = (const float*)d_in[2];
    const float* W_conf   = (const float*)d_in[3];
    const float* b_conf   = (const float*)d_in[4];

    int rows = in_sizes[0] / DIMS;   // 16384

    float* out       = (float*)d_out;
    float* out_boxes = out;
    float* out_conf  = out + (size_t)rows * 12;
    float* out_valid = out + (size_t)rows * 15;

    cudaFuncSetAttribute(det_kernel,
                         cudaFuncAttributeMaxDynamicSharedMemorySize, SMEM_BYTES);

    det_kernel<<<GRID, THREADS, SMEM_BYTES>>>((const float4*)features,
                                              W_bbox, W_conf, b_bbox, b_conf,
                                              out_boxes, out_conf, out_valid, rows);
}